// round 1
// baseline (speedup 1.0000x reference)
#include <cuda_runtime.h>
#include <math.h>

// Problem shape (fixed by setup_inputs): B=4, S=4096, IN=2048, OUT=2048
static constexpr int M = 16384;       // B*S
static constexpr int N = 2048;        // OUT
static constexpr int K = 2048;        // IN
static constexpr long long OUT_ELEMS = (long long)M * N;  // 33554432

// Scratch (no allocations allowed): global fp64 |out| accumulator + final scale.
__device__ double g_abs_sum;
__device__ float  g_scale;

__global__ void k_zero() { g_abs_sum = 0.0; }

// 128x128 tile, BK=8, 256 threads, 8x8 micro-tile per thread.
// A: [M,K] row-major (x), B: [N,K] row-major (qw, ternary floats).
// C[m,n] = s * sum_k A[m,k]*B[n,k]
__global__ __launch_bounds__(256, 2) void k_gemm(
    const float* __restrict__ A,
    const float* __restrict__ B,
    const float* __restrict__ s_in,
    const float* __restrict__ s_w,
    float* __restrict__ C)
{
    __shared__ float As[8][128];
    __shared__ float Bs[8][128];

    const int tid = threadIdx.x;
    const int bm = blockIdx.y << 7;
    const int bn = blockIdx.x << 7;

    // Global load mapping: each thread loads one float4 of A and one of B per K-tile.
    const int lrow = tid >> 1;          // 0..127
    const int lk   = (tid & 1) << 2;    // 0 or 4
    const float* Ag = A + (size_t)(bm + lrow) * K + lk;
    const float* Bg = B + (size_t)(bn + lrow) * K + lk;

    // Compute mapping: 16x16 thread grid, 8x8 outputs each.
    const int tx = (tid & 15) << 3;     // n offset within tile
    const int ty = (tid >> 4) << 3;     // m offset within tile

    float acc[8][8];
    #pragma unroll
    for (int i = 0; i < 8; ++i)
        #pragma unroll
        for (int j = 0; j < 8; ++j) acc[i][j] = 0.0f;

    for (int k0 = 0; k0 < K; k0 += 8) {
        float4 a4 = *reinterpret_cast<const float4*>(Ag);
        float4 b4 = *reinterpret_cast<const float4*>(Bg);
        Ag += 8; Bg += 8;
        As[lk + 0][lrow] = a4.x; As[lk + 1][lrow] = a4.y;
        As[lk + 2][lrow] = a4.z; As[lk + 3][lrow] = a4.w;
        Bs[lk + 0][lrow] = b4.x; Bs[lk + 1][lrow] = b4.y;
        Bs[lk + 2][lrow] = b4.z; Bs[lk + 3][lrow] = b4.w;
        __syncthreads();

        #pragma unroll
        for (int kk = 0; kk < 8; ++kk) {
            float a[8], b[8];
            #pragma unroll
            for (int i = 0; i < 8; ++i) a[i] = As[kk][ty + i];
            #pragma unroll
            for (int j = 0; j < 8; ++j) b[j] = Bs[kk][tx + j];
            #pragma unroll
            for (int i = 0; i < 8; ++i)
                #pragma unroll
                for (int j = 0; j < 8; ++j)
                    acc[i][j] = fmaf(a[i], b[j], acc[i][j]);
        }
        __syncthreads();
    }

    const float s = s_in[0] * s_w[0];
    float asum = 0.0f;
    #pragma unroll
    for (int i = 0; i < 8; ++i) {
        float* crow = C + (size_t)(bm + ty + i) * N + bn + tx;
        #pragma unroll
        for (int j = 0; j < 8; ++j) {
            float v = acc[i][j] * s;
            crow[j] = v;
            asum += fabsf(v);
        }
    }

    // Block-reduce |out| and accumulate globally in fp64 (2048 atomics total).
    __shared__ float red[256];
    red[tid] = asum;
    __syncthreads();
    for (int st = 128; st > 0; st >>= 1) {
        if (tid < st) red[tid] += red[tid + st];
        __syncthreads();
    }
    if (tid == 0) atomicAdd(&g_abs_sum, (double)red[0]);
}

__global__ void k_finalize(float* __restrict__ scale_out)
{
    float sc = (float)(g_abs_sum / (double)OUT_ELEMS);
    sc = fmaxf(sc, 1e-5f);
    g_scale = sc;
    scale_out[0] = sc;
}

// In-place ternary quantization: q = clip(round(v/scale), -1, 1).
// rintf = round-half-to-even, matching jnp.round. float4-vectorized.
__global__ void k_quant(float* __restrict__ C)
{
    long long i = (long long)blockIdx.x * blockDim.x + threadIdx.x;
    float4* p = reinterpret_cast<float4*>(C);
    float4 v = p[i];
    const float sc = g_scale;
    v.x = fminf(fmaxf(rintf(v.x / sc), -1.0f), 1.0f);
    v.y = fminf(fmaxf(rintf(v.y / sc), -1.0f), 1.0f);
    v.z = fminf(fmaxf(rintf(v.z / sc), -1.0f), 1.0f);
    v.w = fminf(fmaxf(rintf(v.w / sc), -1.0f), 1.0f);
    p[i] = v;
}

extern "C" void kernel_launch(void* const* d_in, const int* in_sizes, int n_in,
                              void* d_out, int out_size)
{
    const float* x    = (const float*)d_in[0];  // [B,S,IN] fp32
    const float* s_in = (const float*)d_in[1];  // scalar
    const float* qw   = (const float*)d_in[2];  // [OUT,IN] fp32 ternary
    const float* s_w  = (const float*)d_in[3];  // scalar
    float* out = (float*)d_out;                 // [M*N] q values + [1] scale

    (void)in_sizes; (void)n_in; (void)out_size;

    k_zero<<<1, 1>>>();

    dim3 grid(N / 128, M / 128);   // (16, 128) = 2048 blocks
    k_gemm<<<grid, 256>>>(x, qw, s_in, s_w, out);

    k_finalize<<<1, 1>>>(out + OUT_ELEMS);

    const int qthreads = 256;
    const int qblocks = (int)(OUT_ELEMS / 4 / qthreads);  // 32768
    k_quant<<<qblocks, qthreads>>>(out);
}

// round 9
// speedup vs baseline: 3.2039x; 3.2039x over previous
#include <cuda_runtime.h>
#include <cuda_fp16.h>
#include <math.h>
#include <stdint.h>

// Problem shape (fixed): B=4, S=4096, IN=2048, OUT=2048
static constexpr int M = 16384;
static constexpr int N = 2048;
static constexpr int K = 2048;
static constexpr long long OUT_ELEMS = (long long)M * N;

// GEMM tiling
static constexpr int BM = 128;
static constexpr int BN = 128;
static constexpr int BK = 64;                  // fp16 per chunk: 128 bytes/row
static constexpr int CHUNKS = K / BK;          // 32
static constexpr int THREADS = 512;            // 16 warps: 4 (M) x 4 (N)

// Static scratch (no allocations allowed)
__device__ __align__(16) __half g_xh[(size_t)M * K];   // H plane (digit*4096)
__device__ __align__(16) __half g_xl[(size_t)M * K];   // L plane
__device__ __align__(16) __half g_wh[(size_t)N * K];   // ternary weights fp16
__device__ double g_abs_sum;
__device__ float  g_scale;
__device__ float  g_P;        // power-of-two fixed-point scale
__device__ double g_invP;     // 1/P (exact)

// ---------------- helpers ----------------
__device__ __forceinline__ uint32_t smem_u32(const void* p) {
    uint32_t a;
    asm("{ .reg .u64 t; cvta.to.shared.u64 t, %1; cvt.u32.u64 %0, t; }"
        : "=r"(a) : "l"(p));
    return a;
}
__device__ __forceinline__ uint32_t swz128(uint32_t off) {
    return off ^ ((off >> 3) & 0x70);
}
__device__ __forceinline__ void cp_async16(uint32_t dst, const void* src) {
    asm volatile("cp.async.cg.shared.global [%0], [%1], 16;" :: "r"(dst), "l"(src));
}
__device__ __forceinline__ void cp_commit() {
    asm volatile("cp.async.commit_group;");
}
template <int NG>
__device__ __forceinline__ void cp_wait() {
    asm volatile("cp.async.wait_group %0;" :: "n"(NG));
}
__device__ __forceinline__ void ldsm_x4(uint32_t& r0, uint32_t& r1, uint32_t& r2,
                                        uint32_t& r3, uint32_t addr) {
    asm volatile("ldmatrix.sync.aligned.m8n8.x4.shared.b16 {%0,%1,%2,%3}, [%4];"
                 : "=r"(r0), "=r"(r1), "=r"(r2), "=r"(r3) : "r"(addr));
}
__device__ __forceinline__ void mma16816(float* d, const uint32_t* a,
                                         const uint32_t* b) {
    asm volatile(
        "mma.sync.aligned.m16n8k16.row.col.f32.f16.f16.f32 "
        "{%0,%1,%2,%3}, {%4,%5,%6,%7}, {%8,%9}, {%0,%1,%2,%3};"
        : "+f"(d[0]), "+f"(d[1]), "+f"(d[2]), "+f"(d[3])
        : "r"(a[0]), "r"(a[1]), "r"(a[2]), "r"(a[3]), "r"(b[0]), "r"(b[1]));
}

// ---------------- init: zero accumulator, compute fixed-point scale ----------------
__global__ void k_init(const float* __restrict__ s_in, const float* __restrict__ s_w) {
    g_abs_sum = 0.0;
    float s = s_in[0] * s_w[0];                  // > 0 (s_w >= EPS)
    // P = 2^floor(log2(2^23 / (16*s))): guarantees |X| <= 2^23 for |x| <= 16,
    // hence |H| <= 2048 (exact fp16) and |L| <= 2048 (exact fp16).
    float t = 524288.0f / s;                     // 2^23 / 16 / s
    int e;
    frexpf(t, &e);                               // t = m * 2^e, m in [0.5, 1)
    g_P = ldexpf(1.0f, e - 1);
    g_invP = ldexp(1.0, 1 - e);                  // exact double
}

// qw fp32 ternary -> fp16 (exact)
__global__ void k_prep_w(const float* __restrict__ qw) {
    long long i = ((long long)blockIdx.x * blockDim.x + threadIdx.x) * 4;
    float4 v = *reinterpret_cast<const float4*>(qw + i);
    __half2 p0 = __halves2half2(__float2half_rn(v.x), __float2half_rn(v.y));
    __half2 p1 = __halves2half2(__float2half_rn(v.z), __float2half_rn(v.w));
    uint2 u; u.x = *reinterpret_cast<uint32_t*>(&p0); u.y = *reinterpret_cast<uint32_t*>(&p1);
    *reinterpret_cast<uint2*>(&g_wh[i]) = u;
}

// x -> y = fl(fl(x*s_in)*s_w)  (matches reference's elementwise roundings exactly),
// then exact fixed-point split: X = rint(y*P), H = rint(X/4096), L = X - 4096*H.
__global__ void k_prep_x(const float* __restrict__ x,
                         const float* __restrict__ s_in,
                         const float* __restrict__ s_w) {
    long long i = ((long long)blockIdx.x * blockDim.x + threadIdx.x) * 4;
    const float si = s_in[0], sw = s_w[0], P = g_P;
    float4 v = *reinterpret_cast<const float4*>(x + i);
    float f[4] = {v.x, v.y, v.z, v.w};
    __half H[4], L[4];
    #pragma unroll
    for (int j = 0; j < 4; ++j) {
        float y = (f[j] * si) * sw;              // same roundings as reference products
        float X = rintf(y * P);                  // y*P exact (P pow2); |X| <= 2^23
        float h = rintf(X * (1.0f / 4096.0f));   // |h| <= 2048
        float l = X - h * 4096.0f;               // exact; |l| <= 2048
        H[j] = __float2half_rn(h);               // exact (integers <= 2048)
        L[j] = __float2half_rn(l);
    }
    uint2 uh, ul;
    __half2 t;
    t = __halves2half2(H[0], H[1]); uh.x = *reinterpret_cast<uint32_t*>(&t);
    t = __halves2half2(H[2], H[3]); uh.y = *reinterpret_cast<uint32_t*>(&t);
    t = __halves2half2(L[0], L[1]); ul.x = *reinterpret_cast<uint32_t*>(&t);
    t = __halves2half2(L[2], L[3]); ul.y = *reinterpret_cast<uint32_t*>(&t);
    *reinterpret_cast<uint2*>(&g_xh[i]) = uh;
    *reinterpret_cast<uint2*>(&g_xl[i]) = ul;
}

// ---------------- exact integer GEMM on fp16 tensor cores ----------------
static constexpr int PLANE_BYTES = BM * 128;               // 16 KB
static constexpr int STAGE_A = 2 * PLANE_BYTES;            // 32 KB (H + L)
static constexpr int STAGE_B = BN * 128;                   // 16 KB
static constexpr int STAGE   = STAGE_A + STAGE_B;          // 48 KB
static constexpr int NSTAGES = 3;
static constexpr int SMEM_TOTAL = NSTAGES * STAGE;         // 144 KB

__global__ void __launch_bounds__(THREADS) k_gemm_mma(float* __restrict__ C)
{
    extern __shared__ char smem[];
    __shared__ float red[THREADS];

    const uint32_t sm0 = smem_u32(smem);
    const int tid = threadIdx.x;
    const int wid = tid >> 5;
    const int lid = tid & 31;
    const int wm = wid & 3;          // 4 warps along M (32 rows each)
    const int wn = wid >> 2;         // 4 warps along N (32 cols each)
    const int gid = lid >> 2;
    const int tig = lid & 3;
    const int bm = blockIdx.y * BM;
    const int bn = blockIdx.x * BN;

    // acc[plane][mt][nb][4]
    float acc[2][2][4][4];
    #pragma unroll
    for (int p = 0; p < 2; ++p)
        #pragma unroll
        for (int mt = 0; mt < 2; ++mt)
            #pragma unroll
            for (int j = 0; j < 4; ++j)
                #pragma unroll
                for (int q = 0; q < 4; ++q) acc[p][mt][j][q] = 0.0f;

    // stage loader: chunk c -> stage s
    auto load_stage = [&](int c, int s) {
        const uint32_t base = sm0 + s * STAGE;
        const long long k0 = (long long)c * BK;
        // A: 2 planes x 128 rows x 8 x 16B = 2048 lines -> 4 per thread
        #pragma unroll
        for (int it = 0; it < 4; ++it) {
            int v = tid + it * THREADS;
            int plane = v >> 10;
            int r = (v >> 3) & 127;
            int u = v & 7;
            const __half* src = (plane ? g_xl : g_xh);
            cp_async16(base + plane * PLANE_BYTES + swz128(r * 128 + u * 16),
                       src + (size_t)(bm + r) * K + k0 + u * 8);
        }
        // B: 128 rows x 8 x 16B = 1024 lines -> 2 per thread
        #pragma unroll
        for (int it = 0; it < 2; ++it) {
            int v = tid + it * THREADS;
            int r = v >> 3, u = v & 7;
            cp_async16(base + STAGE_A + swz128(r * 128 + u * 16),
                       g_wh + (size_t)(bn + r) * K + k0 + u * 8);
        }
        cp_commit();
    };

    load_stage(0, 0);
    load_stage(1, 1);

    for (int c = 0; c < CHUNKS; ++c) {
        if (c + 1 < CHUNKS) cp_wait<1>(); else cp_wait<0>();
        __syncthreads();

        if (c + 2 < CHUNKS) load_stage(c + 2, (c + 2) % NSTAGES);

        const uint32_t abase = sm0 + (c % NSTAGES) * STAGE;
        const uint32_t bbase = abase + STAGE_A;

        #pragma unroll
        for (int s = 0; s < 4; ++s) {
            // A fragments: per plane, two 16x16 tiles
            uint32_t a[2][2][4];
            #pragma unroll
            for (int p = 0; p < 2; ++p)
                #pragma unroll
                for (int mt = 0; mt < 2; ++mt) {
                    int r = wm * 32 + mt * 16 + (lid & 15);
                    uint32_t off = p * PLANE_BYTES +
                                   swz128(r * 128 + s * 32 + (lid >> 4) * 16);
                    ldsm_x4(a[p][mt][0], a[p][mt][1], a[p][mt][2], a[p][mt][3],
                            abase + off);
                }
            // B fragments: 4 n8 blocks (warp cols wn*32 .. +31), shared by planes
            uint32_t b[4][2];
            #pragma unroll
            for (int q = 0; q < 2; ++q) {
                int n = wn * 32 + q * 16 + (lid & 7) + ((lid >> 4) << 3);
                uint32_t cb = (lid >> 3) & 1;
                uint32_t off = swz128(n * 128 + s * 32 + cb * 16);
                uint32_t r0, r1, r2, r3;
                ldsm_x4(r0, r1, r2, r3, bbase + off);
                b[2 * q][0] = r0;     b[2 * q][1] = r1;
                b[2 * q + 1][0] = r2; b[2 * q + 1][1] = r3;
            }
            #pragma unroll
            for (int p = 0; p < 2; ++p)
                #pragma unroll
                for (int mt = 0; mt < 2; ++mt)
                    #pragma unroll
                    for (int j = 0; j < 4; ++j)
                        mma16816(acc[p][mt][j], a[p][mt], b[j]);
        }
        __syncthreads();
    }

    // epilogue: exact combine in fp64, store fp32, |v| partial sum
    const double invP = g_invP;
    float asum = 0.0f;
    #pragma unroll
    for (int mt = 0; mt < 2; ++mt) {
        int row0 = bm + wm * 32 + mt * 16 + gid;
        #pragma unroll
        for (int j = 0; j < 4; ++j) {
            int col = bn + wn * 32 + j * 8 + 2 * tig;
            float vv[4];
            #pragma unroll
            for (int q = 0; q < 4; ++q) {
                double comb = ((double)acc[0][mt][j][q] * 4096.0 +
                               (double)acc[1][mt][j][q]) * invP;
                vv[q] = (float)comb;
                asum += fabsf(vv[q]);
            }
            float2 lo, hi;
            lo.x = vv[0]; lo.y = vv[1];
            hi.x = vv[2]; hi.y = vv[3];
            *reinterpret_cast<float2*>(C + (size_t)row0 * N + col) = lo;
            *reinterpret_cast<float2*>(C + (size_t)(row0 + 8) * N + col) = hi;
        }
    }
    red[tid] = asum;
    __syncthreads();
    for (int st = THREADS / 2; st > 0; st >>= 1) {
        if (tid < st) red[tid] += red[tid + st];
        __syncthreads();
    }
    if (tid == 0) atomicAdd(&g_abs_sum, (double)red[0]);
}

// ---------------- finalize + quantize ----------------
__global__ void k_finalize(float* __restrict__ scale_out) {
    float sc = (float)(g_abs_sum / (double)OUT_ELEMS);
    sc = fmaxf(sc, 1e-5f);
    g_scale = sc;
    scale_out[0] = sc;
}

__global__ void k_quant(float* __restrict__ C) {
    long long i = (long long)blockIdx.x * blockDim.x + threadIdx.x;
    float4* p = reinterpret_cast<float4*>(C);
    float4 v = p[i];
    const float sc = g_scale;
    v.x = fminf(fmaxf(rintf(v.x / sc), -1.0f), 1.0f);
    v.y = fminf(fmaxf(rintf(v.y / sc), -1.0f), 1.0f);
    v.z = fminf(fmaxf(rintf(v.z / sc), -1.0f), 1.0f);
    v.w = fminf(fmaxf(rintf(v.w / sc), -1.0f), 1.0f);
    p[i] = v;
}

extern "C" void kernel_launch(void* const* d_in, const int* in_sizes, int n_in,
                              void* d_out, int out_size)
{
    const float* x    = (const float*)d_in[0];
    const float* s_in = (const float*)d_in[1];
    const float* qw   = (const float*)d_in[2];
    const float* s_w  = (const float*)d_in[3];
    float* out = (float*)d_out;
    (void)in_sizes; (void)n_in; (void)out_size;

    cudaFuncSetAttribute(k_gemm_mma, cudaFuncAttributeMaxDynamicSharedMemorySize, SMEM_TOTAL);

    k_init<<<1, 1>>>(s_in, s_w);
    k_prep_w<<<(int)((long long)N * K / 4 / 256), 256>>>(qw);
    k_prep_x<<<(int)((long long)M * K / 4 / 256), 256>>>(x, s_in, s_w);

    dim3 grid(N / BN, M / BM);   // (16, 128) = 2048 CTAs
    k_gemm_mma<<<grid, THREADS, SMEM_TOTAL>>>(out);

    k_finalize<<<1, 1>>>(out + OUT_ELEMS);

    const int qthreads = 256;
    const int qblocks = (int)(OUT_ELEMS / 4 / qthreads);
    k_quant<<<qblocks, qthreads>>>(out);
}